// round 10
// baseline (speedup 1.0000x reference)
#include <cuda_runtime.h>
#include <math.h>

// Problem constants
#define BB     2
#define HEADS  8
#define LEVELS 3
#define POINTS 4
#define CC     256
#define HD     32          // CC / HEADS
#define NV     5376        // 64*64 + 32*32 + 16*16
#define NQ     5376
#define TP     96          // HEADS*LEVELS*POINTS
#define TP2    192

// Padded value-tensor geometry: each level padded by a 1-cell zero ring.
// L0: 66x66 = 4356, L1: 34x34 = 1156, L2: 18x18 = 324.  Total 5836 cells/batch.
#define PNV    5836
#define P0     0
#define P1     4356
#define P2     5512
#define VP_TOTAL  (BB * PNV * CC)      // 2,988,032 floats

// Scratch (static device allocations — allowed by harness rules)
__device__ float g_vp[VP_TOTAL];           // padded value @ Wv^T + bv, (b, padded_cell, h, hd)
__device__ float g_off[BB * NQ * TP2];     // sampling offsets
__device__ float g_a[BB * NQ * TP];        // attention logits (softmax fused in sampler)
__device__ float g_tmp[BB * NQ * CC];      // sampled output, layout (b, q, h, hd)

// ---------------------------------------------------------------------------
// Zero the padded value buffer (border cells must be 0 every call; interior
// is overwritten by the v-GEMM). Full-buffer float4 memset, ~2-3us.
// ---------------------------------------------------------------------------
__global__ void __launch_bounds__(256) zero_vp_kernel()
{
    int i = blockIdx.x * blockDim.x + threadIdx.x;
    if (i < VP_TOTAL / 4)
        ((float4*)g_vp)[i] = make_float4(0.f, 0.f, 0.f, 0.f);
}

// ---------------------------------------------------------------------------
// Tensor-core GEMM (tf32 mma.sync): C[m,n] = sum_k A[m,k]*W[n,k] + bias[n]
// Block tile 64m x 64n, k-tile 32, 128 threads = 4 warps, each warp 32m x 32n
// (2 m16 x 4 n8 of m16n8k8). fp32 accum; inputs rounded to tf32.
// Small CTA footprint -> 4-5 CTAs/SM for latency hiding (R9 was occ-bound).
// Register-prefetch double buffering on the k loop.
// pad_v != 0: epilogue remaps output rows into the padded g_vp layout.
// ---------------------------------------------------------------------------
#define GBm 64
#define GBn 64
#define GBk 32
#define SSTR 36   // smem row stride in words (32 + 4 pad -> conflict-free)

__device__ __forceinline__ unsigned f2tf32(float f) {
    unsigned u;
    asm("cvt.rna.tf32.f32 %0, %1;" : "=r"(u) : "f"(f));
    return u;
}

__device__ __forceinline__ int padded_row(int gm) {
    int b = gm / NV;
    int n = gm - b * NV;
    int pbase, cell;
    if (n < 4096)      { int y = n >> 6, x = n & 63;                   pbase = P0; cell = (y + 1) * 66 + (x + 1); }
    else if (n < 5120) { int t = n - 4096; int y = t >> 5, x = t & 31; pbase = P1; cell = (y + 1) * 34 + (x + 1); }
    else               { int t = n - 5120; int y = t >> 4, x = t & 15; pbase = P2; cell = (y + 1) * 18 + (x + 1); }
    return b * PNV + pbase + cell;
}

__global__ void __launch_bounds__(128) gemm_tf32_kernel(
    const float* __restrict__ A, const float* __restrict__ W,
    const float* __restrict__ bias, float* __restrict__ C,
    int M, int N, int K, int pad_v)
{
    __shared__ unsigned As[GBm][SSTR];   // A tile, [m][k], tf32 bits
    __shared__ unsigned Ws[GBn][SSTR];   // W tile, [n][k], tf32 bits

    const int tid  = threadIdx.x;
    const int lane = tid & 31;
    const int warp = tid >> 5;           // 0..3
    const int wm   = warp >> 1;          // 0..1 -> m offset wm*32
    const int wn   = warp & 1;           // 0..1 -> n offset wn*32
    const int m0   = blockIdx.y * GBm;
    const int n0   = blockIdx.x * GBn;

    const int grp = lane >> 2;           // groupID (0..7)
    const int tig = lane & 3;            // threadID in group (0..3)

    // Per-thread fixed load coordinates: A and W tiles are each
    // 64 rows x 8 float4 = 512 float4 -> 4 per thread at 128 threads.
    int ar[4], ac[4];
    size_t aoff[4];
    int wr[4], wc[4], wg[4];
    size_t woff[4];
#pragma unroll
    for (int j = 0; j < 4; j++) {
        int idx = tid + j * 128;
        ar[j] = idx >> 3;                // 0..63
        ac[j] = idx & 7;                 // float4 index along k
        aoff[j] = (size_t)(m0 + ar[j]) * K + ac[j] * 4;
        wr[j] = ar[j];
        wc[j] = ac[j];
        wg[j] = n0 + wr[j];
        woff[j] = (size_t)wg[j] * K + wc[j] * 4;
    }

    float c[2][4][4];
#pragma unroll
    for (int mt = 0; mt < 2; mt++)
#pragma unroll
        for (int nt = 0; nt < 4; nt++)
#pragma unroll
            for (int i = 0; i < 4; i++) c[mt][nt][i] = 0.f;

    // Prologue: fetch k0 = 0 tile into registers
    float4 pa[4], pw[4];
#pragma unroll
    for (int j = 0; j < 4; j++) pa[j] = *(const float4*)&A[aoff[j]];
#pragma unroll
    for (int j = 0; j < 4; j++)
        pw[j] = (wg[j] < N) ? *(const float4*)&W[woff[j]]
                            : make_float4(0.f, 0.f, 0.f, 0.f);

    for (int k0 = 0; k0 < K; k0 += GBk) {
        // Store prefetched tile (with tf32 rounding) to smem
#pragma unroll
        for (int j = 0; j < 4; j++) {
            uint4 u;
            u.x = f2tf32(pa[j].x); u.y = f2tf32(pa[j].y);
            u.z = f2tf32(pa[j].z); u.w = f2tf32(pa[j].w);
            *(uint4*)&As[ar[j]][ac[j] * 4] = u;
        }
#pragma unroll
        for (int j = 0; j < 4; j++) {
            uint4 u;
            u.x = f2tf32(pw[j].x); u.y = f2tf32(pw[j].y);
            u.z = f2tf32(pw[j].z); u.w = f2tf32(pw[j].w);
            *(uint4*)&Ws[wr[j]][wc[j] * 4] = u;
        }
        __syncthreads();

        // Prefetch next k-tile (LDGs retire under the mma compute below)
        const int kn = k0 + GBk;
        if (kn < K) {
#pragma unroll
            for (int j = 0; j < 4; j++) pa[j] = *(const float4*)&A[aoff[j] + kn];
#pragma unroll
            for (int j = 0; j < 4; j++)
                pw[j] = (wg[j] < N) ? *(const float4*)&W[woff[j] + kn]
                                    : make_float4(0.f, 0.f, 0.f, 0.f);
        }

#pragma unroll
        for (int kk = 0; kk < GBk; kk += 8) {
            unsigned a[2][4];
#pragma unroll
            for (int mt = 0; mt < 2; mt++) {
                int rb = wm * 32 + mt * 16;
                a[mt][0] = As[rb + grp][kk + tig];
                a[mt][1] = As[rb + grp + 8][kk + tig];
                a[mt][2] = As[rb + grp][kk + tig + 4];
                a[mt][3] = As[rb + grp + 8][kk + tig + 4];
            }
            unsigned b[4][2];
#pragma unroll
            for (int nt = 0; nt < 4; nt++) {
                int cb = wn * 32 + nt * 8;
                b[nt][0] = Ws[cb + grp][kk + tig];
                b[nt][1] = Ws[cb + grp][kk + tig + 4];
            }
#pragma unroll
            for (int mt = 0; mt < 2; mt++)
#pragma unroll
                for (int nt = 0; nt < 4; nt++) {
                    asm volatile(
                        "mma.sync.aligned.m16n8k8.row.col.f32.tf32.tf32.f32 "
                        "{%0,%1,%2,%3}, {%4,%5,%6,%7}, {%8,%9}, {%0,%1,%2,%3};"
                        : "+f"(c[mt][nt][0]), "+f"(c[mt][nt][1]),
                          "+f"(c[mt][nt][2]), "+f"(c[mt][nt][3])
                        : "r"(a[mt][0]), "r"(a[mt][1]), "r"(a[mt][2]), "r"(a[mt][3]),
                          "r"(b[nt][0]), "r"(b[nt][1]));
                }
        }
        __syncthreads();
    }

    // ---- epilogue ----
    int row0[2], row1[2];
#pragma unroll
    for (int mt = 0; mt < 2; mt++) {
        int gm = m0 + wm * 32 + mt * 16 + grp;
        row0[mt] = pad_v ? padded_row(gm) : gm;
        row1[mt] = pad_v ? padded_row(gm + 8) : gm + 8;
    }
#pragma unroll
    for (int nt = 0; nt < 4; nt++) {
        int gn = n0 + wn * 32 + nt * 8 + tig * 2;
        if (gn >= N) continue;
        float b0 = bias[gn];
        float b1 = bias[gn + 1];
#pragma unroll
        for (int mt = 0; mt < 2; mt++) {
            float2 o0 = make_float2(c[mt][nt][0] + b0, c[mt][nt][1] + b1);
            float2 o1 = make_float2(c[mt][nt][2] + b0, c[mt][nt][3] + b1);
            *(float2*)&C[(size_t)row0[mt] * N + gn] = o0;
            *(float2*)&C[(size_t)row1[mt] * N + gn] = o1;
        }
    }
}

// ---------------------------------------------------------------------------
// Bilinear sampling, corner-parallel float4 form, zero-padded value tensor:
// no clamps, no validity predicates — out-of-range corners read exact zeros.
// One warp per (b, q, head); lane = cg*8 + ch4.  (unchanged from R9)
// ---------------------------------------------------------------------------
__global__ void __launch_bounds__(256) sample_kernel(
    const float* __restrict__ refpts)
{
    const int warp = (blockIdx.x * blockDim.x + threadIdx.x) >> 5;
    const int lane = threadIdx.x & 31;
    const int total = BB * NQ * HEADS;
    if (warp >= total) return;

    const int h  = warp % HEADS;
    const int bq = warp / HEADS;      // b*NQ + q
    const int b  = bq / NQ;

    const int cg  = lane >> 3;        // corner 0..3
    const int dx  = cg & 1;
    const int dy  = cg >> 1;
    const int ch4 = lane & 7;         // float4 chunk within head

    const float rx = refpts[bq * 2 + 0];
    const float ry = refpts[bq * 2 + 1];

    const float* __restrict__ off   = g_off + bq * TP2 + h * (LEVELS * POINTS * 2);
    const float* __restrict__ logit = g_a   + bq * TP  + h * (LEVELS * POINTS);

    // Fused softmax over the 12 attention logits.
    float e[LEVELS * POINTS];
    float mx = -INFINITY;
#pragma unroll
    for (int i = 0; i < LEVELS * POINTS; i++) {
        e[i] = logit[i];
        mx = fmaxf(mx, e[i]);
    }
    float s = 0.f;
#pragma unroll
    for (int i = 0; i < LEVELS * POINTS; i++) { e[i] = __expf(e[i] - mx); s += e[i]; }
    const float inv = 1.f / s;

    const int plvl_start[LEVELS] = {P0, P1, P2};
    const int lvl_dim[LEVELS]    = {64, 32, 16};

    float4 acc = make_float4(0.f, 0.f, 0.f, 0.f);

#pragma unroll
    for (int lvl = 0; lvl < LEVELS; lvl++) {
        const int Wd = lvl_dim[lvl];
        const int Pw = Wd + 2;        // padded width
        const int base = (b * PNV + plvl_start[lvl]) * CC + h * HD + ch4 * 4;
        const float fW = (float)Wd;
#pragma unroll
        for (int p = 0; p < POINTS; p++) {
            float lx = rx + off[(lvl * POINTS + p) * 2 + 0];
            float ly = ry + off[(lvl * POINTS + p) * 2 + 1];
            lx = fminf(fmaxf(lx, 0.f), 1.f);
            ly = fminf(fmaxf(ly, 0.f), 1.f);
            const float aw = e[lvl * POINTS + p] * inv;

            const float x = lx * fW - 0.5f;
            const float y = ly * fW - 0.5f;   // Hd == Wd for all levels
            const float x0f = floorf(x);
            const float y0f = floorf(y);
            const int x0 = (int)x0f;
            const int y0 = (int)y0f;
            const float wx1 = x - x0f;
            const float wy1 = y - y0f;

            const float w = aw * (dx ? wx1 : 1.f - wx1) * (dy ? wy1 : 1.f - wy1);

            // padded cell: (y0+dy+1, x0+dx+1) — always in range
            const int cell = (y0 + dy + 1) * Pw + (x0 + dx + 1);
            const float4 v4 = *(const float4*)&g_vp[base + cell * CC];

            acc.x = fmaf(w, v4.x, acc.x);
            acc.y = fmaf(w, v4.y, acc.y);
            acc.z = fmaf(w, v4.z, acc.z);
            acc.w = fmaf(w, v4.w, acc.w);
        }
    }

    // Reduce the 4 corner groups (lanes differing in bits 3,4)
#pragma unroll
    for (int ofs = 8; ofs <= 16; ofs <<= 1) {
        acc.x += __shfl_xor_sync(0xffffffffu, acc.x, ofs);
        acc.y += __shfl_xor_sync(0xffffffffu, acc.y, ofs);
        acc.z += __shfl_xor_sync(0xffffffffu, acc.z, ofs);
        acc.w += __shfl_xor_sync(0xffffffffu, acc.w, ofs);
    }

    if (lane < 8) {
        *(float4*)&g_tmp[(bq * HEADS + h) * HD + ch4 * 4] = acc;
    }
}

// ---------------------------------------------------------------------------
extern "C" void kernel_launch(void* const* d_in, const int* in_sizes, int n_in,
                              void* d_out, int out_size)
{
    const float* query  = (const float*)d_in[0];
    const float* refpts = (const float*)d_in[1];
    const float* value  = (const float*)d_in[2];
    const float* Wv     = (const float*)d_in[3];
    const float* bv     = (const float*)d_in[4];
    const float* Woff   = (const float*)d_in[5];
    const float* boff   = (const float*)d_in[6];
    const float* Wa     = (const float*)d_in[7];
    const float* ba     = (const float*)d_in[8];
    const float* Wo     = (const float*)d_in[9];
    const float* bo     = (const float*)d_in[10];
    float* out = (float*)d_out;

    float *p_vp, *p_off, *p_a, *p_tmp;
    cudaGetSymbolAddress((void**)&p_vp,  g_vp);
    cudaGetSymbolAddress((void**)&p_off, g_off);
    cudaGetSymbolAddress((void**)&p_a,   g_a);
    cudaGetSymbolAddress((void**)&p_tmp, g_tmp);

    const int M = BB * NQ;              // 10752 = 168 * 64
    const int gy = M / GBm;             // 168

    // zero padded value buffer (border must be 0; interior overwritten below)
    zero_vp_kernel<<<(VP_TOTAL / 4 + 255) / 256, 256>>>();
    // v = value @ Wv^T + bv  -> padded layout
    gemm_tf32_kernel<<<dim3(CC / GBn, gy), 128>>>(value, Wv, bv, p_vp, M, CC, CC, 1);
    // off = query @ Woff^T + boff
    gemm_tf32_kernel<<<dim3(TP2 / GBn, gy), 128>>>(query, Woff, boff, p_off, M, TP2, CC, 0);
    // a = query @ Wa^T + ba
    gemm_tf32_kernel<<<dim3((TP + GBn - 1) / GBn, gy), 128>>>(query, Wa, ba, p_a, M, TP, CC, 0);
    // bilinear sampling (softmax fused, corner-parallel, padded v)
    sample_kernel<<<(BB * NQ * HEADS) / 8, 256>>>(refpts);
    // out = tmp @ Wo^T + bo
    gemm_tf32_kernel<<<dim3(CC / GBn, gy), 128>>>(p_tmp, Wo, bo, out, M, CC, CC, 0);
}

// round 11
// speedup vs baseline: 1.6354x; 1.6354x over previous
#include <cuda_runtime.h>
#include <math.h>

// Problem constants
#define BB     2
#define HEADS  8
#define LEVELS 3
#define POINTS 4
#define CC     256
#define HD     32          // CC / HEADS
#define NV     5376        // 64*64 + 32*32 + 16*16
#define NQ     5376
#define TP     96          // HEADS*LEVELS*POINTS
#define TP2    192

// Padded value-tensor geometry: each level padded by a 1-cell zero ring.
// L0: 66x66 = 4356, L1: 34x34 = 1156, L2: 18x18 = 324.  Total 5836 cells/batch.
#define PNV    5836
#define P0     0
#define P1     4356
#define P2     5512
#define VP_TOTAL  (BB * PNV * CC)      // 2,988,032 floats

// Scratch (static device allocations — allowed by harness rules)
__device__ float g_vp[VP_TOTAL];           // padded value @ Wv^T + bv, (b, padded_cell, h, hd)
__device__ float g_off[BB * NQ * TP2];     // sampling offsets
__device__ float g_a[BB * NQ * TP];        // attention logits (softmax fused in sampler)
__device__ float g_tmp[BB * NQ * CC];      // sampled output, layout (b, q, h, hd)

// ---------------------------------------------------------------------------
// Zero the padded value buffer (border cells must be 0 every call; interior
// is overwritten by the v-GEMM). Full-buffer float4 memset, ~2-3us.
// ---------------------------------------------------------------------------
__global__ void __launch_bounds__(256) zero_vp_kernel()
{
    int i = blockIdx.x * blockDim.x + threadIdx.x;
    if (i < VP_TOTAL / 4)
        ((float4*)g_vp)[i] = make_float4(0.f, 0.f, 0.f, 0.f);
}

// ---------------------------------------------------------------------------
// Tensor-core GEMM (tf32 mma.sync): C[m,n] = sum_k A[m,k]*W[n,k] + bias[n]
// R9 winner: block tile 128m x 64n, k-tile 32, 256 threads = 8 warps, each
// warp 32m x 32n (2 m16 x 4 n8 of m16n8k8). fp32 accum; tf32-rounded inputs.
// Register-prefetch double buffering. min-blocks 2 occupancy hint.
// pad_v != 0: epilogue remaps output rows into the padded g_vp layout.
// ---------------------------------------------------------------------------
#define GBm 128
#define GBn 64
#define GBk 32
#define SSTR 36   // smem row stride in words (32 + 4 pad -> conflict-free)

__device__ __forceinline__ unsigned f2tf32(float f) {
    unsigned u;
    asm("cvt.rna.tf32.f32 %0, %1;" : "=r"(u) : "f"(f));
    return u;
}

__device__ __forceinline__ int padded_row(int gm) {
    int b = gm / NV;
    int n = gm - b * NV;
    int pbase, cell;
    if (n < 4096)      { int y = n >> 6, x = n & 63;                   pbase = P0; cell = (y + 1) * 66 + (x + 1); }
    else if (n < 5120) { int t = n - 4096; int y = t >> 5, x = t & 31; pbase = P1; cell = (y + 1) * 34 + (x + 1); }
    else               { int t = n - 5120; int y = t >> 4, x = t & 15; pbase = P2; cell = (y + 1) * 18 + (x + 1); }
    return b * PNV + pbase + cell;
}

__global__ void __launch_bounds__(256, 2) gemm_tf32_kernel(
    const float* __restrict__ A, const float* __restrict__ W,
    const float* __restrict__ bias, float* __restrict__ C,
    int M, int N, int K, int pad_v)
{
    __shared__ unsigned As[GBm][SSTR];   // A tile, [m][k], tf32 bits
    __shared__ unsigned Ws[GBn][SSTR];   // W tile, [n][k], tf32 bits

    const int tid  = threadIdx.x;
    const int lane = tid & 31;
    const int warp = tid >> 5;
    const int wm   = warp >> 1;          // 0..3 -> m offset wm*32
    const int wn   = warp & 1;           // 0..1 -> n offset wn*32
    const int m0   = blockIdx.y * GBm;
    const int n0   = blockIdx.x * GBn;

    const int grp = lane >> 2;           // groupID (0..7)
    const int tig = lane & 3;            // threadID in group (0..3)

    // Per-thread fixed load coordinates (A: 4 float4s, W: 2 float4s per tile)
    int ar[4], ac[4];
    size_t aoff[4];
#pragma unroll
    for (int j = 0; j < 4; j++) {
        int idx = tid + j * 256;
        ar[j] = idx >> 3;
        ac[j] = idx & 7;
        aoff[j] = (size_t)(m0 + ar[j]) * K + ac[j] * 4;
    }
    int wr[2], wc[2], wg[2];
    size_t woff[2];
#pragma unroll
    for (int j = 0; j < 2; j++) {
        int idx = tid + j * 256;
        wr[j] = idx >> 3;
        wc[j] = idx & 7;
        wg[j] = n0 + wr[j];
        woff[j] = (size_t)wg[j] * K + wc[j] * 4;
    }

    float c[2][4][4];
#pragma unroll
    for (int mt = 0; mt < 2; mt++)
#pragma unroll
        for (int nt = 0; nt < 4; nt++)
#pragma unroll
            for (int i = 0; i < 4; i++) c[mt][nt][i] = 0.f;

    // Prologue: fetch k0 = 0 tile into registers
    float4 pa[4], pw[2];
#pragma unroll
    for (int j = 0; j < 4; j++) pa[j] = *(const float4*)&A[aoff[j]];
#pragma unroll
    for (int j = 0; j < 2; j++)
        pw[j] = (wg[j] < N) ? *(const float4*)&W[woff[j]]
                            : make_float4(0.f, 0.f, 0.f, 0.f);

    for (int k0 = 0; k0 < K; k0 += GBk) {
        // Store prefetched tile (with tf32 rounding) to smem
#pragma unroll
        for (int j = 0; j < 4; j++) {
            uint4 u;
            u.x = f2tf32(pa[j].x); u.y = f2tf32(pa[j].y);
            u.z = f2tf32(pa[j].z); u.w = f2tf32(pa[j].w);
            *(uint4*)&As[ar[j]][ac[j] * 4] = u;
        }
#pragma unroll
        for (int j = 0; j < 2; j++) {
            uint4 u;
            u.x = f2tf32(pw[j].x); u.y = f2tf32(pw[j].y);
            u.z = f2tf32(pw[j].z); u.w = f2tf32(pw[j].w);
            *(uint4*)&Ws[wr[j]][wc[j] * 4] = u;
        }
        __syncthreads();

        // Prefetch next k-tile (LDGs retire under the mma compute below)
        const int kn = k0 + GBk;
        if (kn < K) {
#pragma unroll
            for (int j = 0; j < 4; j++) pa[j] = *(const float4*)&A[aoff[j] + kn];
#pragma unroll
            for (int j = 0; j < 2; j++)
                pw[j] = (wg[j] < N) ? *(const float4*)&W[woff[j] + kn]
                                    : make_float4(0.f, 0.f, 0.f, 0.f);
        }

#pragma unroll
        for (int kk = 0; kk < GBk; kk += 8) {
            unsigned a[2][4];
#pragma unroll
            for (int mt = 0; mt < 2; mt++) {
                int rb = wm * 32 + mt * 16;
                a[mt][0] = As[rb + grp][kk + tig];
                a[mt][1] = As[rb + grp + 8][kk + tig];
                a[mt][2] = As[rb + grp][kk + tig + 4];
                a[mt][3] = As[rb + grp + 8][kk + tig + 4];
            }
            unsigned b[4][2];
#pragma unroll
            for (int nt = 0; nt < 4; nt++) {
                int cb = wn * 32 + nt * 8;
                b[nt][0] = Ws[cb + grp][kk + tig];
                b[nt][1] = Ws[cb + grp][kk + tig + 4];
            }
#pragma unroll
            for (int mt = 0; mt < 2; mt++)
#pragma unroll
                for (int nt = 0; nt < 4; nt++) {
                    asm volatile(
                        "mma.sync.aligned.m16n8k8.row.col.f32.tf32.tf32.f32 "
                        "{%0,%1,%2,%3}, {%4,%5,%6,%7}, {%8,%9}, {%0,%1,%2,%3};"
                        : "+f"(c[mt][nt][0]), "+f"(c[mt][nt][1]),
                          "+f"(c[mt][nt][2]), "+f"(c[mt][nt][3])
                        : "r"(a[mt][0]), "r"(a[mt][1]), "r"(a[mt][2]), "r"(a[mt][3]),
                          "r"(b[nt][0]), "r"(b[nt][1]));
                }
        }
        __syncthreads();
    }

    // ---- epilogue ----
    int row0[2], row1[2];
#pragma unroll
    for (int mt = 0; mt < 2; mt++) {
        int gm = m0 + wm * 32 + mt * 16 + grp;
        row0[mt] = pad_v ? padded_row(gm) : gm;
        row1[mt] = pad_v ? padded_row(gm + 8) : gm + 8;
    }
#pragma unroll
    for (int nt = 0; nt < 4; nt++) {
        int gn = n0 + wn * 32 + nt * 8 + tig * 2;
        if (gn >= N) continue;
        float b0 = bias[gn];
        float b1 = bias[gn + 1];
#pragma unroll
        for (int mt = 0; mt < 2; mt++) {
            float2 o0 = make_float2(c[mt][nt][0] + b0, c[mt][nt][1] + b1);
            float2 o1 = make_float2(c[mt][nt][2] + b0, c[mt][nt][3] + b1);
            *(float2*)&C[(size_t)row0[mt] * N + gn] = o0;
            *(float2*)&C[(size_t)row1[mt] * N + gn] = o1;
        }
    }
}

// ---------------------------------------------------------------------------
// Bilinear sampling, corner-parallel float4 form, zero-padded value tensor.
// One warp per (b, q, head); lane = cg*8 + ch4.  (unchanged from R9)
// ---------------------------------------------------------------------------
__global__ void __launch_bounds__(256) sample_kernel(
    const float* __restrict__ refpts)
{
    const int warp = (blockIdx.x * blockDim.x + threadIdx.x) >> 5;
    const int lane = threadIdx.x & 31;
    const int total = BB * NQ * HEADS;
    if (warp >= total) return;

    const int h  = warp % HEADS;
    const int bq = warp / HEADS;      // b*NQ + q
    const int b  = bq / NQ;

    const int cg  = lane >> 3;        // corner 0..3
    const int dx  = cg & 1;
    const int dy  = cg >> 1;
    const int ch4 = lane & 7;         // float4 chunk within head

    const float rx = refpts[bq * 2 + 0];
    const float ry = refpts[bq * 2 + 1];

    const float* __restrict__ off   = g_off + bq * TP2 + h * (LEVELS * POINTS * 2);
    const float* __restrict__ logit = g_a   + bq * TP  + h * (LEVELS * POINTS);

    // Fused softmax over the 12 attention logits.
    float e[LEVELS * POINTS];
    float mx = -INFINITY;
#pragma unroll
    for (int i = 0; i < LEVELS * POINTS; i++) {
        e[i] = logit[i];
        mx = fmaxf(mx, e[i]);
    }
    float s = 0.f;
#pragma unroll
    for (int i = 0; i < LEVELS * POINTS; i++) { e[i] = __expf(e[i] - mx); s += e[i]; }
    const float inv = 1.f / s;

    const int plvl_start[LEVELS] = {P0, P1, P2};
    const int lvl_dim[LEVELS]    = {64, 32, 16};

    float4 acc = make_float4(0.f, 0.f, 0.f, 0.f);

#pragma unroll
    for (int lvl = 0; lvl < LEVELS; lvl++) {
        const int Wd = lvl_dim[lvl];
        const int Pw = Wd + 2;        // padded width
        const int base = (b * PNV + plvl_start[lvl]) * CC + h * HD + ch4 * 4;
        const float fW = (float)Wd;
#pragma unroll
        for (int p = 0; p < POINTS; p++) {
            float lx = rx + off[(lvl * POINTS + p) * 2 + 0];
            float ly = ry + off[(lvl * POINTS + p) * 2 + 1];
            lx = fminf(fmaxf(lx, 0.f), 1.f);
            ly = fminf(fmaxf(ly, 0.f), 1.f);
            const float aw = e[lvl * POINTS + p] * inv;

            const float x = lx * fW - 0.5f;
            const float y = ly * fW - 0.5f;   // Hd == Wd for all levels
            const float x0f = floorf(x);
            const float y0f = floorf(y);
            const int x0 = (int)x0f;
            const int y0 = (int)y0f;
            const float wx1 = x - x0f;
            const float wy1 = y - y0f;

            const float w = aw * (dx ? wx1 : 1.f - wx1) * (dy ? wy1 : 1.f - wy1);

            // padded cell: (y0+dy+1, x0+dx+1) — always in range
            const int cell = (y0 + dy + 1) * Pw + (x0 + dx + 1);
            const float4 v4 = *(const float4*)&g_vp[base + cell * CC];

            acc.x = fmaf(w, v4.x, acc.x);
            acc.y = fmaf(w, v4.y, acc.y);
            acc.z = fmaf(w, v4.z, acc.z);
            acc.w = fmaf(w, v4.w, acc.w);
        }
    }

    // Reduce the 4 corner groups (lanes differing in bits 3,4)
#pragma unroll
    for (int ofs = 8; ofs <= 16; ofs <<= 1) {
        acc.x += __shfl_xor_sync(0xffffffffu, acc.x, ofs);
        acc.y += __shfl_xor_sync(0xffffffffu, acc.y, ofs);
        acc.z += __shfl_xor_sync(0xffffffffu, acc.z, ofs);
        acc.w += __shfl_xor_sync(0xffffffffu, acc.w, ofs);
    }

    if (lane < 8) {
        *(float4*)&g_tmp[(bq * HEADS + h) * HD + ch4 * 4] = acc;
    }
}

// ---------------------------------------------------------------------------
extern "C" void kernel_launch(void* const* d_in, const int* in_sizes, int n_in,
                              void* d_out, int out_size)
{
    const float* query  = (const float*)d_in[0];
    const float* refpts = (const float*)d_in[1];
    const float* value  = (const float*)d_in[2];
    const float* Wv     = (const float*)d_in[3];
    const float* bv     = (const float*)d_in[4];
    const float* Woff   = (const float*)d_in[5];
    const float* boff   = (const float*)d_in[6];
    const float* Wa     = (const float*)d_in[7];
    const float* ba     = (const float*)d_in[8];
    const float* Wo     = (const float*)d_in[9];
    const float* bo     = (const float*)d_in[10];
    float* out = (float*)d_out;

    float *p_vp, *p_off, *p_a, *p_tmp;
    cudaGetSymbolAddress((void**)&p_vp,  g_vp);
    cudaGetSymbolAddress((void**)&p_off, g_off);
    cudaGetSymbolAddress((void**)&p_a,   g_a);
    cudaGetSymbolAddress((void**)&p_tmp, g_tmp);

    // Side streams + events for graph-level parallelism. Created once (first,
    // non-captured correctness call); on the capture call only the launches,
    // event records and waits execute — all capture-legal, identical each call.
    static cudaStream_t s1 = nullptr, s2 = nullptr;
    static cudaEvent_t ev_root = nullptr, ev_off = nullptr, ev_a = nullptr;
    if (!s1) {
        cudaStreamCreateWithFlags(&s1, cudaStreamNonBlocking);
        cudaStreamCreateWithFlags(&s2, cudaStreamNonBlocking);
        cudaEventCreateWithFlags(&ev_root, cudaEventDisableTiming);
        cudaEventCreateWithFlags(&ev_off,  cudaEventDisableTiming);
        cudaEventCreateWithFlags(&ev_a,    cudaEventDisableTiming);
    }

    const int M = BB * NQ;              // 10752 = 84 * 128
    const int gy = M / GBm;             // 84

    // Fork: side streams join the capture graph via the root event.
    cudaEventRecord(ev_root, 0);
    cudaStreamWaitEvent(s1, ev_root, 0);
    cudaStreamWaitEvent(s2, ev_root, 0);

    // Main stream: zero padded v buffer, then v-GEMM into it.
    zero_vp_kernel<<<(VP_TOTAL / 4 + 255) / 256, 256>>>();
    gemm_tf32_kernel<<<dim3(CC / GBn, gy), 256>>>(value, Wv, bv, p_vp, M, CC, CC, 1);

    // Side stream 1: off = query @ Woff^T + boff
    gemm_tf32_kernel<<<dim3(TP2 / GBn, gy), 256, 0, s1>>>(query, Woff, boff, p_off, M, TP2, CC, 0);
    cudaEventRecord(ev_off, s1);

    // Side stream 2: a = query @ Wa^T + ba
    gemm_tf32_kernel<<<dim3((TP + GBn - 1) / GBn, gy), 256, 0, s2>>>(query, Wa, ba, p_a, M, TP, CC, 0);
    cudaEventRecord(ev_a, s2);

    // Join: sampler needs v, off, a.
    cudaStreamWaitEvent(0, ev_off, 0);
    cudaStreamWaitEvent(0, ev_a, 0);

    // bilinear sampling (softmax fused, corner-parallel, padded v)
    sample_kernel<<<(BB * NQ * HEADS) / 8, 256>>>(refpts);
    // out = tmp @ Wo^T + bo
    gemm_tf32_kernel<<<dim3(CC / GBn, gy), 256>>>(p_tmp, Wo, bo, out, M, CC, CC, 0);
}